// round 12
// baseline (speedup 1.0000x reference)
#include <cuda_runtime.h>
#include <math.h>

#define B_    4
#define C_    256
#define H_    128
#define W_    128
#define HW    (H_*W_)          // 16384
#define NTOK  (B_*HW)          // 65536
#define SCALE 0.08838834764831845f
#define EPS   1e-4f

typedef unsigned long long ull;
typedef unsigned int uint32;

// ---------------- bf16 helpers ----------------
__device__ __forceinline__ uint32 pkbf(float lo, float hi) {
    uint32 d; asm("cvt.rn.bf16x2.f32 %0, %1, %2;" : "=r"(d) : "f"(hi), "f"(lo)); return d;
}
__device__ __forceinline__ float bflo(uint32 w){ return __uint_as_float(w << 16); }
__device__ __forceinline__ float bfhi(uint32 w){ return __uint_as_float(w & 0xffff0000u); }
__device__ __forceinline__ uint2 splitbf(float v0, float v1) {
    uint32 hw = pkbf(v0, v1);
    uint32 lw = pkbf(v0 - bflo(hw), v1 - bfhi(hw));
    return make_uint2(hw, lw);
}

__device__ __forceinline__ void mmabf(float* d, const uint32* a, uint32 b0, uint32 b1) {
    asm volatile("mma.sync.aligned.m16n8k16.row.col.f32.bf16.bf16.f32 "
        "{%0,%1,%2,%3}, {%4,%5,%6,%7}, {%8,%9}, {%0,%1,%2,%3};"
        : "+f"(d[0]), "+f"(d[1]), "+f"(d[2]), "+f"(d[3])
        : "r"(a[0]), "r"(a[1]), "r"(a[2]), "r"(a[3]), "r"(b0), "r"(b1));
}
__device__ __forceinline__ void ldmT(uint32& r0, uint32& r1, uint32& r2, uint32& r3, uint32 addr) {
    asm volatile("ldmatrix.sync.aligned.m8n8.x4.trans.shared.b16 {%0,%1,%2,%3}, [%4];"
        : "=r"(r0), "=r"(r1), "=r"(r2), "=r"(r3) : "r"(addr));
}
__device__ __forceinline__ uint32 smem_u32(const void* p) {
    uint32 a;
    asm("{ .reg .u64 t; cvta.to.shared.u64 t, %1; cvt.u32.u64 %0, t; }" : "=r"(a) : "l"(p));
    return a;
}

// ---------------- scratch: interleaved bf16 hi/lo planes (uint2 = {hi,lo}) ----------------
__device__ uint2  g_xn [(size_t)NTOK * 128];
__device__ uint2  g_qkv[(size_t)NTOK * 384];    // [t][384w], head-deinterleaved, q pre-scaled
__device__ float  g_xc [(size_t)NTOK * C_];     // lepe fp32, PERMUTED channels [br][head][d]
__device__ uint2  g_xcb[(size_t)NTOK * 128];    // attn+lepe bf16 (permuted)
__device__ uint2  g_wq [768 * 128];
__device__ uint2  g_pw [256 * 128];             // proj W, columns permuted

template<int BR>
__device__ __forceinline__ int win_tok(int win, int s) {
    int b  = win >> 5;
    int wi = win & 31;
    int y, x;
    if (BR == 0) { y = s >> 2;               x = (wi << 2) + (s & 3); }
    else         { y = (wi << 2) + (s >> 7); x = s & 127; }
    return b * HW + y * W_ + x;
}

// ---------------- 1) LayerNorm ----------------
__global__ void __launch_bounds__(256) ln_kernel(const float* __restrict__ x,
                                                 const float* __restrict__ gam,
                                                 const float* __restrict__ bet) {
    __shared__ float xs[C_][33];
    __shared__ float mu_s[32], rs_s[32];
    int tid = threadIdx.x;
    int tx = tid & 31, ty = tid >> 5;
    int t0 = blockIdx.x * 32;
    int b  = t0 / HW;
    int pp = t0 - b * HW;
    const float* xb = x + (size_t)b * C_ * HW + pp + tx;
    #pragma unroll
    for (int c = ty; c < C_; c += 8)
        xs[c][tx] = xb[(size_t)c * HW];
    __syncthreads();
    if (tid < 32) {
        float s = 0.f, s2 = 0.f;
        #pragma unroll 8
        for (int c = 0; c < C_; c++) { float v = xs[c][tid]; s += v; s2 += v * v; }
        float mu  = s * (1.0f / C_);
        float var = s2 * (1.0f / C_) - mu * mu;
        mu_s[tid] = mu;
        rs_s[tid] = rsqrtf(var + EPS);
    }
    __syncthreads();
    for (int idx = tid; idx < 32 * 128; idx += 256) {
        int c2 = idx & 127, tk = idx >> 7;
        int c = c2 * 2;
        float v0 = (xs[c][tk]     - mu_s[tk]) * rs_s[tk] * gam[c]     + bet[c];
        float v1 = (xs[c + 1][tk] - mu_s[tk]) * rs_s[tk] * gam[c + 1] + bet[c + 1];
        g_xn[(size_t)(t0 + tk) * 128 + c2] = splitbf(v0, v1);
    }
}

// ---------------- 1b) weight splits ----------------
__global__ void __launch_bounds__(256) w_split(const float* __restrict__ wqkv,
                                               const float* __restrict__ projw) {
    int idx = blockIdx.x * 256 + threadIdx.x;
    if (idx < 768 * 128) {
        int n = idx >> 7, kw = idx & 127;
        float v0 = wqkv[(size_t)(2 * kw) * 768 + n];
        float v1 = wqkv[(size_t)(2 * kw + 1) * 768 + n];
        g_wq[idx] = splitbf(v0, v1);
    }
    if (idx < 256 * 128) {
        int o = idx >> 7, kw = idx & 127;
        int pc = 2 * kw;
        int br = pc >> 7, rm = pc & 127;
        int head = rm >> 6, d = rm & 63;
        int c0 = br * 128 + 2 * d + head;
        float v0 = projw[(size_t)o * 256 + c0];
        float v1 = projw[(size_t)o * 256 + c0 + 2];
        g_pw[idx] = splitbf(v0, v1);
    }
}

// ---------------- bf16 3-product GEMM core ----------------
#define GAH 0
#define GAL 2560
#define GBH 5120
#define GBL 7680
#define SMEM_GEMM_BYTES (16512 * 4)

extern __shared__ uint32 smw[];

__device__ __forceinline__ void bf_mainloop(
        const uint2* __restrict__ A, const uint2* __restrict__ Bm,
        int m0, int n0, float acc[4][4][4]) {
    int tid  = threadIdx.x;
    int wid  = tid >> 5, lane = tid & 31;
    int wm   = (wid & 1) * 64;
    int wn   = (wid >> 1) * 32;
    int grp  = lane >> 2, tig = lane & 3;

    for (int ck = 0; ck < 8; ck++) {
        int k0w = ck * 16;
        __syncthreads();
        #pragma unroll
        for (int idx = tid; idx < 2048; idx += 256) {
            int r = idx >> 4, w = idx & 15;
            int so = r * 20 + w;
            uint2 va = A [(size_t)(m0 + r) * 128 + k0w + w];
            uint2 vb = Bm[(size_t)(n0 + r) * 128 + k0w + w];
            smw[GAH + so] = va.x;
            smw[GAL + so] = va.y;
            smw[GBH + so] = vb.x;
            smw[GBL + so] = vb.y;
        }
        __syncthreads();
        #pragma unroll
        for (int ks = 0; ks < 2; ks++) {
            uint32 bh[4][2], bl[4][2];
            #pragma unroll
            for (int j = 0; j < 4; j++) {
                int nb = (wn + j * 8 + grp) * 20 + ks * 8 + tig;
                bh[j][0] = smw[GBH + nb]; bh[j][1] = smw[GBH + nb + 4];
                bl[j][0] = smw[GBL + nb]; bl[j][1] = smw[GBL + nb + 4];
            }
            #pragma unroll
            for (int i = 0; i < 4; i++) {
                int mb = (wm + i * 16 + grp) * 20 + ks * 8 + tig;
                uint32 ah[4], al[4];
                ah[0] = smw[GAH + mb];        ah[1] = smw[GAH + mb + 160];
                ah[2] = smw[GAH + mb + 4];    ah[3] = smw[GAH + mb + 164];
                al[0] = smw[GAL + mb];        al[1] = smw[GAL + mb + 160];
                al[2] = smw[GAL + mb + 4];    al[3] = smw[GAL + mb + 164];
                #pragma unroll
                for (int j = 0; j < 4; j++) {
                    mmabf(acc[i][j], ah, bh[j][0], bh[j][1]);
                    mmabf(acc[i][j], ah, bl[j][0], bl[j][1]);
                    mmabf(acc[i][j], al, bh[j][0], bh[j][1]);
                }
            }
        }
    }
    __syncthreads();
    float* smf = (float*)smw;
    #pragma unroll
    for (int i = 0; i < 4; i++)
        #pragma unroll
        for (int j = 0; j < 4; j++) {
            int m = wm + i * 16 + grp;
            int n = wn + j * 8 + tig * 2;
            smf[m * 129 + n]           = acc[i][j][0];
            smf[m * 129 + n + 1]       = acc[i][j][1];
            smf[(m + 8) * 129 + n]     = acc[i][j][2];
            smf[(m + 8) * 129 + n + 1] = acc[i][j][3];
        }
    __syncthreads();
}

// ---------------- 2) QKV GEMM ----------------
__global__ void __launch_bounds__(256) gemm_qkv_bf() {
    float acc[4][4][4] = {};
    int m0 = blockIdx.y * 128;
    int n0 = blockIdx.x * 128;
    bf_mainloop(g_xn, g_wq, m0, n0, acc);
    const float* smf = (const float*)smw;
    int tid = threadIdx.x;
    float sc = (n0 < 256) ? SCALE : 1.0f;
    for (int i = tid; i < 128 * 64; i += 256) {
        int m = i >> 6, e = i & 63;
        int head = e >> 5, d = (e & 31) * 2;
        int c0 = 2 * d + head;
        float v0 = smf[m * 129 + c0] * sc;
        float v1 = smf[m * 129 + c0 + 2] * sc;
        g_qkv[(size_t)(m0 + m) * 384 + (n0 >> 1) + e] = splitbf(v0, v1);
    }
}

// ---------------- 5) Proj GEMM ----------------
__global__ void __launch_bounds__(256) gemm_proj_bf(const float* __restrict__ Pb,
                                                    float* __restrict__ out) {
    float acc[4][4][4] = {};
    int m0 = blockIdx.y * 128;
    int n0 = blockIdx.x * 128;
    bf_mainloop(g_xcb, g_pw, m0, n0, acc);
    const float* smf = (const float*)smw;
    int tid = threadIdx.x;
    int b  = m0 >> 14;
    int pp = m0 & (HW - 1);
    int mm = tid & 127;
    int oh = tid >> 7;
    float* Op = out + (size_t)b * C_ * HW + pp + mm;
    #pragma unroll 4
    for (int oo = 0; oo < 64; oo++) {
        int o = n0 + oh * 64 + oo;
        Op[(size_t)o * HW] = smf[mm * 129 + oh * 64 + oo] + Pb[o];
    }
}

// ---------------- 3) LePE — image-neighbor form, one uint2 per tap ----------------
template<int BR>
__global__ void __launch_bounds__(256) lepe_t(const float* __restrict__ wt,
                                              const float* __restrict__ bs) {
    __shared__ float ws[128 * 9];
    __shared__ float bss[128];
    int tid = threadIdx.x;
    for (int i = tid; i < 128 * 9; i += 256) ws[i] = wt[i];
    if (tid < 128) bss[tid] = bs[tid];
    __syncthreads();
    int ew = tid & 63;
    int t  = blockIdx.x * 4 + (tid >> 6);
    int y  = (t >> 7) & 127, x = t & 127;
    int vw = 256 + BR * 64 + ew;
    int cc0 = 4 * (ew & 31) + (ew >> 5);
    int cc1 = cc0 + 2;
    float a0 = bss[cc0], a1 = bss[cc1];
    bool um, dm, lm, rm;
    if (BR == 0) { um = y > 0;       dm = y < 127;      lm = (x & 3) > 0; rm = (x & 3) < 3; }
    else         { um = (y & 3) > 0; dm = (y & 3) < 3;  lm = x > 0;       rm = x < 127; }
    #pragma unroll
    for (int ki = 0; ki < 3; ki++) {
        if (ki == 0 && !um) continue;
        if (ki == 2 && !dm) continue;
        int tb = t + (ki - 1) * W_;
        #pragma unroll
        for (int kj = 0; kj < 3; kj++) {
            if (kj == 0 && !lm) continue;
            if (kj == 2 && !rm) continue;
            uint2 hv = g_qkv[(size_t)(tb + kj - 1) * 384 + vw];
            float w0 = ws[cc0 * 9 + ki * 3 + kj];
            float w1 = ws[cc1 * 9 + ki * 3 + kj];
            a0 += w0 * (bflo(hv.x) + bflo(hv.y));
            a1 += w1 * (bfhi(hv.x) + bfhi(hv.y));
        }
    }
    *(float2*)&g_xc[(size_t)t * 256 + BR * 128 + 2 * ew] = make_float2(a0, a1);
}

// ---------------- 4) Flash attention — K-chunk register prefetch ----------------
#define AQH 0
#define AQL 4608
#define AKH 9216
#define AKL 11520
#define AVH 13824
#define AVL 16128
#define SMEM_ATTN_BYTES (18432 * 4)

extern __shared__ uint32 smaw[];
template<int BR>
__global__ void __launch_bounds__(256, 2) attn_flash() {
    int qt   = blockIdx.x;
    int head = blockIdx.y;
    int win  = blockIdx.z;
    int tid  = threadIdx.x;
    int wid  = tid >> 5, lane = tid & 31;
    int grp  = lane >> 2, tig = lane & 3;
    int basew = BR * 64 + head * 32;
    uint32 smbase = smem_u32(smaw);

    // Q tile
    for (int idx = tid; idx < 4096; idx += 256) {
        int r = idx >> 5, w = idx & 31;
        int t = win_tok<BR>(win, qt * 128 + r);
        uint2 q = g_qkv[(size_t)t * 384 + basew + w];
        smaw[AQH + r * 36 + w] = q.x;
        smaw[AQL + r * 36 + w] = q.y;
    }
    __syncthreads();

    uint32 qh[4][4], ql[4][4];
    {
        int rb = (wid * 16 + grp) * 36 + tig;
        #pragma unroll
        for (int ks = 0; ks < 4; ks++) {
            int o = rb + ks * 8;
            qh[ks][0] = smaw[AQH + o];       qh[ks][1] = smaw[AQH + o + 288];
            qh[ks][2] = smaw[AQH + o + 4];   qh[ks][3] = smaw[AQH + o + 292];
            ql[ks][0] = smaw[AQL + o];       ql[ks][1] = smaw[AQL + o + 288];
            ql[ks][2] = smaw[AQL + o + 4];   ql[ks][3] = smaw[AQL + o + 292];
        }
    }

    float o_acc[8][4] = {};
    float m0 = -1e30f, m1 = -1e30f, l0 = 0.f, l1 = 0.f;

    // prefetch K chunk 0
    uint2 rK[8];
    #pragma unroll
    for (int i = 0; i < 8; i++) {
        int idx = i * 256 + tid;
        int r = idx >> 5, w = idx & 31;
        int t = win_tok<BR>(win, r);
        rK[i] = g_qkv[(size_t)t * 384 + 128 + basew + w];
    }

    for (int ck = 0; ck < 8; ck++) {
        __syncthreads();        // previous consumers of K/V regions done
        // store prefetched K, load V straight through
        #pragma unroll
        for (int i = 0; i < 8; i++) {
            int idx = i * 256 + tid;
            int r = idx >> 5, w = idx & 31;
            int so = r * 36 + w;
            smaw[AKH + so] = rK[i].x;
            smaw[AKL + so] = rK[i].y;
            int t = win_tok<BR>(win, ck * 64 + r);
            uint2 v = g_qkv[(size_t)t * 384 + 256 + basew + w];
            smaw[AVH + so] = v.x;
            smaw[AVL + so] = v.y;
        }
        __syncthreads();
        // prefetch next K chunk (LDG latency hides behind mma below)
        if (ck < 7) {
            #pragma unroll
            for (int i = 0; i < 8; i++) {
                int idx = i * 256 + tid;
                int r = idx >> 5, w = idx & 31;
                int t = win_tok<BR>(win, (ck + 1) * 64 + r);
                rK[i] = g_qkv[(size_t)t * 384 + 128 + basew + w];
            }
        }

        // ---- S = Q K^T ----
        float s[8][4];
        #pragma unroll
        for (int j = 0; j < 8; j++) {
            s[j][0] = s[j][1] = s[j][2] = s[j][3] = 0.f;
            #pragma unroll
            for (int ks = 0; ks < 4; ks++) {
                int nb = (j * 8 + grp) * 36 + ks * 8 + tig;
                uint32 bh0 = smaw[AKH + nb], bh1 = smaw[AKH + nb + 4];
                uint32 bl0 = smaw[AKL + nb], bl1 = smaw[AKL + nb + 4];
                mmabf(s[j], qh[ks], bh0, bh1);
                mmabf(s[j], qh[ks], bl0, bl1);
                mmabf(s[j], ql[ks], bh0, bh1);
            }
        }

        // ---- online softmax ----
        float mx0 = s[0][0], mx1 = s[0][2];
        #pragma unroll
        for (int j = 0; j < 8; j++) {
            mx0 = fmaxf(mx0, fmaxf(s[j][0], s[j][1]));
            mx1 = fmaxf(mx1, fmaxf(s[j][2], s[j][3]));
        }
        mx0 = fmaxf(mx0, __shfl_xor_sync(0xffffffffu, mx0, 1));
        mx0 = fmaxf(mx0, __shfl_xor_sync(0xffffffffu, mx0, 2));
        mx1 = fmaxf(mx1, __shfl_xor_sync(0xffffffffu, mx1, 1));
        mx1 = fmaxf(mx1, __shfl_xor_sync(0xffffffffu, mx1, 2));
        float mn0 = fmaxf(m0, mx0), mn1 = fmaxf(m1, mx1);
        float sf0 = __expf(m0 - mn0), sf1 = __expf(m1 - mn1);
        m0 = mn0; m1 = mn1;
        float rs0 = 0.f, rs1 = 0.f;
        #pragma unroll
        for (int j = 0; j < 8; j++) {
            s[j][0] = __expf(s[j][0] - m0); rs0 += s[j][0];
            s[j][1] = __expf(s[j][1] - m0); rs0 += s[j][1];
            s[j][2] = __expf(s[j][2] - m1); rs1 += s[j][2];
            s[j][3] = __expf(s[j][3] - m1); rs1 += s[j][3];
        }
        rs0 += __shfl_xor_sync(0xffffffffu, rs0, 1);
        rs0 += __shfl_xor_sync(0xffffffffu, rs0, 2);
        rs1 += __shfl_xor_sync(0xffffffffu, rs1, 1);
        rs1 += __shfl_xor_sync(0xffffffffu, rs1, 2);
        l0 = l0 * sf0 + rs0;
        l1 = l1 * sf1 + rs1;
        #pragma unroll
        for (int j = 0; j < 8; j++) {
            o_acc[j][0] *= sf0; o_acc[j][1] *= sf0;
            o_acc[j][2] *= sf1; o_acc[j][3] *= sf1;
        }

        // ---- O += P V, P fragments built per-ks (saves registers) ----
        int p2 = lane >> 3, rr = lane & 7;
        #pragma unroll
        for (int ks = 0; ks < 4; ks++) {
            int j0 = 2 * ks, j1 = 2 * ks + 1;
            uint32 ph[4], pl[4];
            ph[0] = pkbf(s[j0][0], s[j0][1]);
            ph[1] = pkbf(s[j0][2], s[j0][3]);
            ph[2] = pkbf(s[j1][0], s[j1][1]);
            ph[3] = pkbf(s[j1][2], s[j1][3]);
            pl[0] = pkbf(s[j0][0] - bflo(ph[0]), s[j0][1] - bfhi(ph[0]));
            pl[1] = pkbf(s[j0][2] - bflo(ph[1]), s[j0][3] - bfhi(ph[1]));
            pl[2] = pkbf(s[j1][0] - bflo(ph[2]), s[j1][1] - bfhi(ph[2]));
            pl[3] = pkbf(s[j1][2] - bflo(ph[3]), s[j1][3] - bfhi(ph[3]));
            int key = 16 * ks + ((p2 & 1) << 3) + rr;
            #pragma unroll
            for (int jp = 0; jp < 4; jp++) {
                int dw = (16 * jp + ((p2 >> 1) << 3)) >> 1;
                uint32 aH = smbase + (AVH + key * 36 + dw) * 4;
                uint32 aL = smbase + (AVL + key * 36 + dw) * 4;
                uint32 vh0, vh1, vh2, vh3, vl0, vl1, vl2, vl3;
                ldmT(vh0, vh1, vh2, vh3, aH);
                ldmT(vl0, vl1, vl2, vl3, aL);
                mmabf(o_acc[2 * jp],     ph, vh0, vh1);
                mmabf(o_acc[2 * jp],     ph, vl0, vl1);
                mmabf(o_acc[2 * jp],     pl, vh0, vh1);
                mmabf(o_acc[2 * jp + 1], ph, vh2, vh3);
                mmabf(o_acc[2 * jp + 1], ph, vl2, vl3);
                mmabf(o_acc[2 * jp + 1], pl, vh2, vh3);
            }
        }
    }

    // ---- epilogue: + LePE, write bf16 planes (permuted, interleaved) ----
    float i0 = 1.0f / l0, i1 = 1.0f / l1;
    int r0 = qt * 128 + wid * 16 + grp;
    int t0 = win_tok<BR>(win, r0);
    int t1 = win_tok<BR>(win, r0 + 8);
    int cb  = BR * 128 + head * 64;
    int wb0 = BR * 64 + head * 32;
    #pragma unroll
    for (int j = 0; j < 8; j++) {
        int d = j * 8 + 2 * tig;
        float2 le0 = *(const float2*)&g_xc[(size_t)t0 * 256 + cb + d];
        float2 le1 = *(const float2*)&g_xc[(size_t)t1 * 256 + cb + d];
        float a0 = le0.x + o_acc[j][0] * i0;
        float a1 = le0.y + o_acc[j][1] * i0;
        float b0 = le1.x + o_acc[j][2] * i1;
        float b1 = le1.y + o_acc[j][3] * i1;
        int wx = wb0 + j * 4 + tig;
        g_xcb[(size_t)t0 * 128 + wx] = splitbf(a0, a1);
        g_xcb[(size_t)t1 * 128 + wx] = splitbf(b0, b1);
    }
}

// ---------------- launch ----------------
extern "C" void kernel_launch(void* const* d_in, const int* in_sizes, int n_in,
                              void* d_out, int out_size) {
    const float* x       = (const float*)d_in[0];
    const float* ln_g    = (const float*)d_in[1];
    const float* ln_b    = (const float*)d_in[2];
    const float* w_qkv   = (const float*)d_in[3];
    const float* lepe_w1 = (const float*)d_in[4];
    const float* lepe_b1 = (const float*)d_in[5];
    const float* lepe_w2 = (const float*)d_in[6];
    const float* lepe_b2 = (const float*)d_in[7];
    const float* proj_w  = (const float*)d_in[8];
    const float* proj_b  = (const float*)d_in[9];
    float* out = (float*)d_out;

    cudaFuncSetAttribute(gemm_qkv_bf,  cudaFuncAttributeMaxDynamicSharedMemorySize, SMEM_GEMM_BYTES);
    cudaFuncSetAttribute(gemm_proj_bf, cudaFuncAttributeMaxDynamicSharedMemorySize, SMEM_GEMM_BYTES);
    cudaFuncSetAttribute(attn_flash<0>, cudaFuncAttributeMaxDynamicSharedMemorySize, SMEM_ATTN_BYTES);
    cudaFuncSetAttribute(attn_flash<1>, cudaFuncAttributeMaxDynamicSharedMemorySize, SMEM_ATTN_BYTES);

    ln_kernel   <<< NTOK / 32, 256 >>>(x, ln_g, ln_b);
    w_split     <<< 384, 256 >>>(w_qkv, proj_w);
    gemm_qkv_bf <<< dim3(6, 512), 256, SMEM_GEMM_BYTES >>>();
    lepe_t<0>   <<< NTOK / 4, 256 >>>(lepe_w1, lepe_b1);
    lepe_t<1>   <<< NTOK / 4, 256 >>>(lepe_w2, lepe_b2);
    attn_flash<0> <<< dim3(4, 2, 128), 256, SMEM_ATTN_BYTES >>>();
    attn_flash<1> <<< dim3(4, 2, 128), 256, SMEM_ATTN_BYTES >>>();
    gemm_proj_bf <<< dim3(2, 512), 256, SMEM_GEMM_BYTES >>>(proj_b, out);
}

// round 14
// speedup vs baseline: 1.3479x; 1.3479x over previous
#include <cuda_runtime.h>
#include <math.h>

#define B_    4
#define C_    256
#define H_    128
#define W_    128
#define HW    (H_*W_)          // 16384
#define NTOK  (B_*HW)          // 65536
#define SCALE 0.08838834764831845f
#define EPS   1e-4f

typedef unsigned long long ull;
typedef unsigned int uint32;

// ---------------- bf16 helpers ----------------
__device__ __forceinline__ uint32 pkbf(float lo, float hi) {
    uint32 d; asm("cvt.rn.bf16x2.f32 %0, %1, %2;" : "=r"(d) : "f"(hi), "f"(lo)); return d;
}
__device__ __forceinline__ float bflo(uint32 w){ return __uint_as_float(w << 16); }
__device__ __forceinline__ float bfhi(uint32 w){ return __uint_as_float(w & 0xffff0000u); }

__device__ __forceinline__ void mmabf(float* d, const uint32* a, uint32 b0, uint32 b1) {
    asm volatile("mma.sync.aligned.m16n8k16.row.col.f32.bf16.bf16.f32 "
        "{%0,%1,%2,%3}, {%4,%5,%6,%7}, {%8,%9}, {%0,%1,%2,%3};"
        : "+f"(d[0]), "+f"(d[1]), "+f"(d[2]), "+f"(d[3])
        : "r"(a[0]), "r"(a[1]), "r"(a[2]), "r"(a[3]), "r"(b0), "r"(b1));
}
__device__ __forceinline__ void ldmT(uint32& r0, uint32& r1, uint32& r2, uint32& r3, uint32 addr) {
    asm volatile("ldmatrix.sync.aligned.m8n8.x4.trans.shared.b16 {%0,%1,%2,%3}, [%4];"
        : "=r"(r0), "=r"(r1), "=r"(r2), "=r"(r3) : "r"(addr));
}
__device__ __forceinline__ uint32 smem_u32(const void* p) {
    uint32 a;
    asm("{ .reg .u64 t; cvta.to.shared.u64 t, %1; cvt.u32.u64 %0, t; }" : "=r"(a) : "l"(p));
    return a;
}
#define CPA4(dst, src)  asm volatile("cp.async.ca.shared.global [%0], [%1], 4;" :: "r"(dst), "l"(src) : "memory")
#define CPA_COMMIT()    asm volatile("cp.async.commit_group;" ::: "memory")
#define CPA_WAIT(n)     asm volatile("cp.async.wait_group %0;" :: "n"(n) : "memory")

// ---------------- scratch (bf16 planes as packed uint32 words) ----------------
__device__ uint32 g_xnh[(size_t)NTOK * 128];
__device__ uint32 g_xnl[(size_t)NTOK * 128];
__device__ uint32 g_qkvh[(size_t)NTOK * 384];   // [t][384w], head-deinterleaved, q pre-scaled
__device__ uint32 g_qkvl[(size_t)NTOK * 384];
__device__ float  g_xc [(size_t)NTOK * C_];     // lepe fp32, PERMUTED channels [br][head][d]
__device__ uint32 g_xch[(size_t)NTOK * 128];    // attn+lepe hi (permuted)
__device__ uint32 g_xcl[(size_t)NTOK * 128];
__device__ uint32 g_wqh[768 * 128];
__device__ uint32 g_wql[768 * 128];
__device__ uint32 g_pwh[256 * 128];             // proj W, columns permuted
__device__ uint32 g_pwl[256 * 128];

template<int BR>
__device__ __forceinline__ int win_tok(int win, int s) {
    int b  = win >> 5;
    int wi = win & 31;
    int y, x;
    if (BR == 0) { y = s >> 2;               x = (wi << 2) + (s & 3); }
    else         { y = (wi << 2) + (s >> 7); x = s & 127; }
    return b * HW + y * W_ + x;
}

// ---------------- 1) LayerNorm -> bf16 hi/lo planes ----------------
__global__ void __launch_bounds__(256) ln_kernel(const float* __restrict__ x,
                                                 const float* __restrict__ gam,
                                                 const float* __restrict__ bet) {
    __shared__ float xs[C_][33];
    __shared__ float mu_s[32], rs_s[32];
    int tid = threadIdx.x;
    int tx = tid & 31, ty = tid >> 5;
    int t0 = blockIdx.x * 32;
    int b  = t0 / HW;
    int pp = t0 - b * HW;
    const float* xb = x + (size_t)b * C_ * HW + pp + tx;
    #pragma unroll
    for (int c = ty; c < C_; c += 8)
        xs[c][tx] = xb[(size_t)c * HW];
    __syncthreads();
    if (tid < 32) {
        float s = 0.f, s2 = 0.f;
        #pragma unroll 8
        for (int c = 0; c < C_; c++) { float v = xs[c][tid]; s += v; s2 += v * v; }
        float mu  = s * (1.0f / C_);
        float var = s2 * (1.0f / C_) - mu * mu;
        mu_s[tid] = mu;
        rs_s[tid] = rsqrtf(var + EPS);
    }
    __syncthreads();
    for (int idx = tid; idx < 32 * 128; idx += 256) {
        int c2 = idx & 127, tk = idx >> 7;
        int c = c2 * 2;
        float v0 = (xs[c][tk]     - mu_s[tk]) * rs_s[tk] * gam[c]     + bet[c];
        float v1 = (xs[c + 1][tk] - mu_s[tk]) * rs_s[tk] * gam[c + 1] + bet[c + 1];
        uint32 hw = pkbf(v0, v1);
        uint32 lw = pkbf(v0 - bflo(hw), v1 - bfhi(hw));
        size_t o = (size_t)(t0 + tk) * 128 + c2;
        g_xnh[o] = hw;
        g_xnl[o] = lw;
    }
}

// ---------------- 1b) weight splits (proj columns permuted) ----------------
__global__ void __launch_bounds__(256) w_split(const float* __restrict__ wqkv,
                                               const float* __restrict__ projw) {
    int idx = blockIdx.x * 256 + threadIdx.x;
    if (idx < 768 * 128) {
        int n = idx >> 7, kw = idx & 127;
        float v0 = wqkv[(size_t)(2 * kw) * 768 + n];
        float v1 = wqkv[(size_t)(2 * kw + 1) * 768 + n];
        uint32 hw = pkbf(v0, v1);
        g_wqh[idx] = hw;
        g_wql[idx] = pkbf(v0 - bflo(hw), v1 - bfhi(hw));
    }
    if (idx < 256 * 128) {
        int o = idx >> 7, kw = idx & 127;
        int pc = 2 * kw;
        int br = pc >> 7, rm = pc & 127;
        int head = rm >> 6, d = rm & 63;
        int c0 = br * 128 + 2 * d + head;
        float v0 = projw[(size_t)o * 256 + c0];
        float v1 = projw[(size_t)o * 256 + c0 + 2];
        uint32 hw = pkbf(v0, v1);
        g_pwh[idx] = hw;
        g_pwl[idx] = pkbf(v0 - bflo(hw), v1 - bfhi(hw));
    }
}

// ---------------- bf16 3-product GEMM core ----------------
#define GAH 0
#define GAL 2560
#define GBH 5120
#define GBL 7680
#define SMEM_GEMM_BYTES (16512 * 4)

extern __shared__ uint32 smw[];

__device__ __forceinline__ void bf_mainloop(
        const uint32* __restrict__ Ah, const uint32* __restrict__ Al,
        const uint32* __restrict__ Bh, const uint32* __restrict__ Bl,
        int m0, int n0, float acc[4][4][4]) {
    int tid  = threadIdx.x;
    int wid  = tid >> 5, lane = tid & 31;
    int wm   = (wid & 1) * 64;
    int wn   = (wid >> 1) * 32;
    int grp  = lane >> 2, tig = lane & 3;

    for (int ck = 0; ck < 8; ck++) {
        int k0w = ck * 16;
        __syncthreads();
        #pragma unroll
        for (int idx = tid; idx < 2048; idx += 256) {
            int r = idx >> 4, w = idx & 15;
            int so = r * 20 + w;
            size_t ga = (size_t)(m0 + r) * 128 + k0w + w;
            size_t gb = (size_t)(n0 + r) * 128 + k0w + w;
            smw[GAH + so] = Ah[ga];
            smw[GAL + so] = Al[ga];
            smw[GBH + so] = Bh[gb];
            smw[GBL + so] = Bl[gb];
        }
        __syncthreads();
        #pragma unroll
        for (int ks = 0; ks < 2; ks++) {
            uint32 bh[4][2], bl[4][2];
            #pragma unroll
            for (int j = 0; j < 4; j++) {
                int nb = (wn + j * 8 + grp) * 20 + ks * 8 + tig;
                bh[j][0] = smw[GBH + nb]; bh[j][1] = smw[GBH + nb + 4];
                bl[j][0] = smw[GBL + nb]; bl[j][1] = smw[GBL + nb + 4];
            }
            #pragma unroll
            for (int i = 0; i < 4; i++) {
                int mb = (wm + i * 16 + grp) * 20 + ks * 8 + tig;
                uint32 ah[4], al[4];
                ah[0] = smw[GAH + mb];        ah[1] = smw[GAH + mb + 160];
                ah[2] = smw[GAH + mb + 4];    ah[3] = smw[GAH + mb + 164];
                al[0] = smw[GAL + mb];        al[1] = smw[GAL + mb + 160];
                al[2] = smw[GAL + mb + 4];    al[3] = smw[GAL + mb + 164];
                #pragma unroll
                for (int j = 0; j < 4; j++) {
                    mmabf(acc[i][j], ah, bh[j][0], bh[j][1]);
                    mmabf(acc[i][j], ah, bl[j][0], bl[j][1]);
                    mmabf(acc[i][j], al, bh[j][0], bh[j][1]);
                }
            }
        }
    }
    __syncthreads();
    float* smf = (float*)smw;
    #pragma unroll
    for (int i = 0; i < 4; i++)
        #pragma unroll
        for (int j = 0; j < 4; j++) {
            int m = wm + i * 16 + grp;
            int n = wn + j * 8 + tig * 2;
            smf[m * 129 + n]           = acc[i][j][0];
            smf[m * 129 + n + 1]       = acc[i][j][1];
            smf[(m + 8) * 129 + n]     = acc[i][j][2];
            smf[(m + 8) * 129 + n + 1] = acc[i][j][3];
        }
    __syncthreads();
}

// ---------------- 2) QKV GEMM -> permuted bf16 planes (q pre-scaled) ----------------
__global__ void __launch_bounds__(256) gemm_qkv_bf() {
    float acc[4][4][4] = {};
    int m0 = blockIdx.y * 128;
    int n0 = blockIdx.x * 128;
    bf_mainloop(g_xnh, g_xnl, g_wqh, g_wql, m0, n0, acc);
    const float* smf = (const float*)smw;
    int tid = threadIdx.x;
    float sc = (n0 < 256) ? SCALE : 1.0f;
    for (int i = tid; i < 128 * 64; i += 256) {
        int m = i >> 6, e = i & 63;
        int head = e >> 5, d = (e & 31) * 2;
        int c0 = 2 * d + head;
        float v0 = smf[m * 129 + c0] * sc;
        float v1 = smf[m * 129 + c0 + 2] * sc;
        uint32 hw = pkbf(v0, v1);
        uint32 lw = pkbf(v0 - bflo(hw), v1 - bfhi(hw));
        size_t o = (size_t)(m0 + m) * 384 + (n0 >> 1) + e;
        g_qkvh[o] = hw;
        g_qkvl[o] = lw;
    }
}

// ---------------- 5) Proj GEMM -> channel-major fp32 out + bias ----------------
__global__ void __launch_bounds__(256) gemm_proj_bf(const float* __restrict__ Pb,
                                                    float* __restrict__ out) {
    float acc[4][4][4] = {};
    int m0 = blockIdx.y * 128;
    int n0 = blockIdx.x * 128;
    bf_mainloop(g_xch, g_xcl, g_pwh, g_pwl, m0, n0, acc);
    const float* smf = (const float*)smw;
    int tid = threadIdx.x;
    int b  = m0 >> 14;
    int pp = m0 & (HW - 1);
    int mm = tid & 127;
    int oh = tid >> 7;
    float* Op = out + (size_t)b * C_ * HW + pp + mm;
    #pragma unroll 4
    for (int oo = 0; oo < 64; oo++) {
        int o = n0 + oh * 64 + oo;
        Op[(size_t)o * HW] = smf[mm * 129 + oh * 64 + oo] + Pb[o];
    }
}

// ---------------- 3) LePE — image-neighbor form, 2 channels/thread ----------------
template<int BR>
__global__ void __launch_bounds__(256) lepe_t(const float* __restrict__ wt,
                                              const float* __restrict__ bs) {
    __shared__ float ws[128 * 9];
    __shared__ float bss[128];
    int tid = threadIdx.x;
    for (int i = tid; i < 128 * 9; i += 256) ws[i] = wt[i];
    if (tid < 128) bss[tid] = bs[tid];
    __syncthreads();
    int ew = tid & 63;
    int t  = blockIdx.x * 4 + (tid >> 6);
    int y  = (t >> 7) & 127, x = t & 127;
    int vw = 256 + BR * 64 + ew;
    int cc0 = 4 * (ew & 31) + (ew >> 5);
    int cc1 = cc0 + 2;
    float a0 = bss[cc0], a1 = bss[cc1];
    bool um, dm, lm, rm;
    if (BR == 0) { um = y > 0;       dm = y < 127;      lm = (x & 3) > 0; rm = (x & 3) < 3; }
    else         { um = (y & 3) > 0; dm = (y & 3) < 3;  lm = x > 0;       rm = x < 127; }
    #pragma unroll
    for (int ki = 0; ki < 3; ki++) {
        if (ki == 0 && !um) continue;
        if (ki == 2 && !dm) continue;
        int tb = t + (ki - 1) * W_;
        #pragma unroll
        for (int kj = 0; kj < 3; kj++) {
            if (kj == 0 && !lm) continue;
            if (kj == 2 && !rm) continue;
            size_t g = (size_t)(tb + kj - 1) * 384 + vw;
            uint32 hw = g_qkvh[g], lw = g_qkvl[g];
            float w0 = ws[cc0 * 9 + ki * 3 + kj];
            float w1 = ws[cc1 * 9 + ki * 3 + kj];
            a0 += w0 * (bflo(hw) + bflo(lw));
            a1 += w1 * (bfhi(hw) + bfhi(lw));
        }
    }
    *(float2*)&g_xc[(size_t)t * 256 + BR * 128 + 2 * ew] = make_float2(a0, a1);
}

// ---------------- 4) Flash attention — cp.async double-buffered K/V ----------------
// regions (words): QH 0 (128*36), QL 4608; buffers b=0/1 at 9216+b*9216:
//   KH +0, KL +2304, VH +4608, VL +6912  (each 64*36)
#define AQH 0
#define AQL 4608
#define SMEM_ATTN_BYTES (27648 * 4)   // 110,592 B -> 2 CTAs/SM

extern __shared__ uint32 smaw[];
template<int BR>
__global__ void __launch_bounds__(256, 2) attn_flash() {
    int qt   = blockIdx.x;
    int head = blockIdx.y;
    int win  = blockIdx.z;
    int tid  = threadIdx.x;
    int wid  = tid >> 5, lane = tid & 31;
    int grp  = lane >> 2, tig = lane & 3;
    int basew = BR * 64 + head * 32;
    uint32 smbase = smem_u32(smaw);

    // issue K/V chunk 0 into buffer 0 (async), then load Q tile
    {
        int kb = 9216;
        #pragma unroll
        for (int i = 0; i < 8; i++) {
            int idx = i * 256 + tid;
            int r = idx >> 5, w = idx & 31;
            int t = win_tok<BR>(win, r);
            size_t gk = (size_t)t * 384 + 128 + basew + w;
            size_t gv = (size_t)t * 384 + 256 + basew + w;
            uint32 so = smbase + (kb + r * 36 + w) * 4;
            CPA4(so,            g_qkvh + gk);
            CPA4(so + 2304 * 4, g_qkvl + gk);
            CPA4(so + 4608 * 4, g_qkvh + gv);
            CPA4(so + 6912 * 4, g_qkvl + gv);
        }
        CPA_COMMIT();
    }
    for (int idx = tid; idx < 4096; idx += 256) {
        int r = idx >> 5, w = idx & 31;
        int t = win_tok<BR>(win, qt * 128 + r);
        size_t g = (size_t)t * 384 + basew + w;
        smaw[AQH + r * 36 + w] = g_qkvh[g];
        smaw[AQL + r * 36 + w] = g_qkvl[g];
    }
    __syncthreads();

    uint32 qh[4][4], ql[4][4];
    {
        int rb = (wid * 16 + grp) * 36 + tig;
        #pragma unroll
        for (int ks = 0; ks < 4; ks++) {
            int o = rb + ks * 8;
            qh[ks][0] = smaw[AQH + o];       qh[ks][1] = smaw[AQH + o + 288];
            qh[ks][2] = smaw[AQH + o + 4];   qh[ks][3] = smaw[AQH + o + 292];
            ql[ks][0] = smaw[AQL + o];       ql[ks][1] = smaw[AQL + o + 288];
            ql[ks][2] = smaw[AQL + o + 4];   ql[ks][3] = smaw[AQL + o + 292];
        }
    }

    float o_acc[8][4] = {};
    float m0 = -1e30f, m1 = -1e30f, l0 = 0.f, l1 = 0.f;

    for (int ck = 0; ck < 8; ck++) {
        // issue next chunk into alternate buffer (overlaps with this chunk's compute)
        if (ck < 7) {
            int kb = 9216 + ((ck + 1) & 1) * 9216;
            #pragma unroll
            for (int i = 0; i < 8; i++) {
                int idx = i * 256 + tid;
                int r = idx >> 5, w = idx & 31;
                int t = win_tok<BR>(win, (ck + 1) * 64 + r);
                size_t gk = (size_t)t * 384 + 128 + basew + w;
                size_t gv = (size_t)t * 384 + 256 + basew + w;
                uint32 so = smbase + (kb + r * 36 + w) * 4;
                CPA4(so,            g_qkvh + gk);
                CPA4(so + 2304 * 4, g_qkvl + gk);
                CPA4(so + 4608 * 4, g_qkvh + gv);
                CPA4(so + 6912 * 4, g_qkvl + gv);
            }
            CPA_COMMIT();
            CPA_WAIT(1);           // chunk ck complete (groups retire in order)
        } else {
            CPA_WAIT(0);
        }
        __syncthreads();           // all threads' chunk-ck data visible

        int kb  = 9216 + (ck & 1) * 9216;
        int akh = kb, akl = kb + 2304, avh = kb + 4608, avl = kb + 6912;

        // ---- S = Q K^T ----
        float s[8][4];
        #pragma unroll
        for (int j = 0; j < 8; j++) {
            s[j][0] = s[j][1] = s[j][2] = s[j][3] = 0.f;
            #pragma unroll
            for (int ks = 0; ks < 4; ks++) {
                int nb = (j * 8 + grp) * 36 + ks * 8 + tig;
                uint32 bh0 = smaw[akh + nb], bh1 = smaw[akh + nb + 4];
                uint32 bl0 = smaw[akl + nb], bl1 = smaw[akl + nb + 4];
                mmabf(s[j], qh[ks], bh0, bh1);
                mmabf(s[j], qh[ks], bl0, bl1);
                mmabf(s[j], ql[ks], bh0, bh1);
            }
        }

        // ---- online softmax ----
        float mx0 = s[0][0], mx1 = s[0][2];
        #pragma unroll
        for (int j = 0; j < 8; j++) {
            mx0 = fmaxf(mx0, fmaxf(s[j][0], s[j][1]));
            mx1 = fmaxf(mx1, fmaxf(s[j][2], s[j][3]));
        }
        mx0 = fmaxf(mx0, __shfl_xor_sync(0xffffffffu, mx0, 1));
        mx0 = fmaxf(mx0, __shfl_xor_sync(0xffffffffu, mx0, 2));
        mx1 = fmaxf(mx1, __shfl_xor_sync(0xffffffffu, mx1, 1));
        mx1 = fmaxf(mx1, __shfl_xor_sync(0xffffffffu, mx1, 2));
        float mn0 = fmaxf(m0, mx0), mn1 = fmaxf(m1, mx1);
        float sf0 = __expf(m0 - mn0), sf1 = __expf(m1 - mn1);
        m0 = mn0; m1 = mn1;
        float rs0 = 0.f, rs1 = 0.f;
        #pragma unroll
        for (int j = 0; j < 8; j++) {
            s[j][0] = __expf(s[j][0] - m0); rs0 += s[j][0];
            s[j][1] = __expf(s[j][1] - m0); rs0 += s[j][1];
            s[j][2] = __expf(s[j][2] - m1); rs1 += s[j][2];
            s[j][3] = __expf(s[j][3] - m1); rs1 += s[j][3];
        }
        rs0 += __shfl_xor_sync(0xffffffffu, rs0, 1);
        rs0 += __shfl_xor_sync(0xffffffffu, rs0, 2);
        rs1 += __shfl_xor_sync(0xffffffffu, rs1, 1);
        rs1 += __shfl_xor_sync(0xffffffffu, rs1, 2);
        l0 = l0 * sf0 + rs0;
        l1 = l1 * sf1 + rs1;
        #pragma unroll
        for (int j = 0; j < 8; j++) {
            o_acc[j][0] *= sf0; o_acc[j][1] *= sf0;
            o_acc[j][2] *= sf1; o_acc[j][3] *= sf1;
        }

        // ---- O += P V, P fragments built per-ks ----
        int p2 = lane >> 3, rr = lane & 7;
        #pragma unroll
        for (int ks = 0; ks < 4; ks++) {
            int j0 = 2 * ks, j1 = 2 * ks + 1;
            uint32 ph[4], pl[4];
            ph[0] = pkbf(s[j0][0], s[j0][1]);
            ph[1] = pkbf(s[j0][2], s[j0][3]);
            ph[2] = pkbf(s[j1][0], s[j1][1]);
            ph[3] = pkbf(s[j1][2], s[j1][3]);
            pl[0] = pkbf(s[j0][0] - bflo(ph[0]), s[j0][1] - bfhi(ph[0]));
            pl[1] = pkbf(s[j0][2] - bflo(ph[1]), s[j0][3] - bfhi(ph[1]));
            pl[2] = pkbf(s[j1][0] - bflo(ph[2]), s[j1][1] - bfhi(ph[2]));
            pl[3] = pkbf(s[j1][2] - bflo(ph[3]), s[j1][3] - bfhi(ph[3]));
            int key = 16 * ks + ((p2 & 1) << 3) + rr;
            #pragma unroll
            for (int jp = 0; jp < 4; jp++) {
                int dw = (16 * jp + ((p2 >> 1) << 3)) >> 1;
                uint32 aH = smbase + (avh + key * 36 + dw) * 4;
                uint32 aL = smbase + (avl + key * 36 + dw) * 4;
                uint32 vh0, vh1, vh2, vh3, vl0, vl1, vl2, vl3;
                ldmT(vh0, vh1, vh2, vh3, aH);
                ldmT(vl0, vl1, vl2, vl3, aL);
                mmabf(o_acc[2 * jp],     ph, vh0, vh1);
                mmabf(o_acc[2 * jp],     ph, vl0, vl1);
                mmabf(o_acc[2 * jp],     pl, vh0, vh1);
                mmabf(o_acc[2 * jp + 1], ph, vh2, vh3);
                mmabf(o_acc[2 * jp + 1], ph, vl2, vl3);
                mmabf(o_acc[2 * jp + 1], pl, vh2, vh3);
            }
        }
        __syncthreads();   // protect buffer (ck&1) before iteration ck+2 overwrites it
    }

    // ---- epilogue: + LePE, write bf16 planes (permuted) ----
    float i0 = 1.0f / l0, i1 = 1.0f / l1;
    int r0 = qt * 128 + wid * 16 + grp;
    int t0 = win_tok<BR>(win, r0);
    int t1 = win_tok<BR>(win, r0 + 8);
    int cb  = BR * 128 + head * 64;
    int wb0 = BR * 64 + head * 32;
    #pragma unroll
    for (int j = 0; j < 8; j++) {
        int d = j * 8 + 2 * tig;
        float2 le0 = *(const float2*)&g_xc[(size_t)t0 * 256 + cb + d];
        float2 le1 = *(const float2*)&g_xc[(size_t)t1 * 256 + cb + d];
        float a0 = le0.x + o_acc[j][0] * i0;
        float a1 = le0.y + o_acc[j][1] * i0;
        float b0 = le1.x + o_acc[j][2] * i1;
        float b1 = le1.y + o_acc[j][3] * i1;
        int wx = wb0 + j * 4 + tig;
        uint32 h0 = pkbf(a0, a1);
        g_xch[(size_t)t0 * 128 + wx] = h0;
        g_xcl[(size_t)t0 * 128 + wx] = pkbf(a0 - bflo(h0), a1 - bfhi(h0));
        uint32 h1 = pkbf(b0, b1);
        g_xch[(size_t)t1 * 128 + wx] = h1;
        g_xcl[(size_t)t1 * 128 + wx] = pkbf(b0 - bflo(h1), b1 - bfhi(h1));
    }
}

// ---------------- launch ----------------
extern "C" void kernel_launch(void* const* d_in, const int* in_sizes, int n_in,
                              void* d_out, int out_size) {
    const float* x       = (const float*)d_in[0];
    const float* ln_g    = (const float*)d_in[1];
    const float* ln_b    = (const float*)d_in[2];
    const float* w_qkv   = (const float*)d_in[3];
    const float* lepe_w1 = (const float*)d_in[4];
    const float* lepe_b1 = (const float*)d_in[5];
    const float* lepe_w2 = (const float*)d_in[6];
    const float* lepe_b2 = (const float*)d_in[7];
    const float* proj_w  = (const float*)d_in[8];
    const float* proj_b  = (const float*)d_in[9];
    float* out = (float*)d_out;

    cudaFuncSetAttribute(gemm_qkv_bf,  cudaFuncAttributeMaxDynamicSharedMemorySize, SMEM_GEMM_BYTES);
    cudaFuncSetAttribute(gemm_proj_bf, cudaFuncAttributeMaxDynamicSharedMemorySize, SMEM_GEMM_BYTES);
    cudaFuncSetAttribute(attn_flash<0>, cudaFuncAttributeMaxDynamicSharedMemorySize, SMEM_ATTN_BYTES);
    cudaFuncSetAttribute(attn_flash<1>, cudaFuncAttributeMaxDynamicSharedMemorySize, SMEM_ATTN_BYTES);

    ln_kernel   <<< NTOK / 32, 256 >>>(x, ln_g, ln_b);
    w_split     <<< 384, 256 >>>(w_qkv, proj_w);
    gemm_qkv_bf <<< dim3(6, 512), 256, SMEM_GEMM_BYTES >>>();
    lepe_t<0>   <<< NTOK / 4, 256 >>>(lepe_w1, lepe_b1);
    lepe_t<1>   <<< NTOK / 4, 256 >>>(lepe_w2, lepe_b2);
    attn_flash<0> <<< dim3(4, 2, 128), 256, SMEM_ATTN_BYTES >>>();
    attn_flash<1> <<< dim3(4, 2, 128), 256, SMEM_ATTN_BYTES >>>();
    gemm_proj_bf <<< dim3(2, 512), 256, SMEM_GEMM_BYTES >>>(proj_b, out);
}

// round 15
// speedup vs baseline: 1.5698x; 1.1647x over previous
#include <cuda_runtime.h>
#include <math.h>

#define B_    4
#define C_    256
#define H_    128
#define W_    128
#define HW    (H_*W_)          // 16384
#define NTOK  (B_*HW)          // 65536
#define SCALE 0.08838834764831845f
#define EPS   1e-4f

typedef unsigned long long ull;
typedef unsigned int uint32;

// ---------------- bf16 helpers ----------------
__device__ __forceinline__ uint32 pkbf(float lo, float hi) {
    uint32 d; asm("cvt.rn.bf16x2.f32 %0, %1, %2;" : "=r"(d) : "f"(hi), "f"(lo)); return d;
}
__device__ __forceinline__ float bflo(uint32 w){ return __uint_as_float(w << 16); }
__device__ __forceinline__ float bfhi(uint32 w){ return __uint_as_float(w & 0xffff0000u); }

__device__ __forceinline__ void mmabf(float* d, const uint32* a, uint32 b0, uint32 b1) {
    asm volatile("mma.sync.aligned.m16n8k16.row.col.f32.bf16.bf16.f32 "
        "{%0,%1,%2,%3}, {%4,%5,%6,%7}, {%8,%9}, {%0,%1,%2,%3};"
        : "+f"(d[0]), "+f"(d[1]), "+f"(d[2]), "+f"(d[3])
        : "r"(a[0]), "r"(a[1]), "r"(a[2]), "r"(a[3]), "r"(b0), "r"(b1));
}
__device__ __forceinline__ void ldmT(uint32& r0, uint32& r1, uint32& r2, uint32& r3, uint32 addr) {
    asm volatile("ldmatrix.sync.aligned.m8n8.x4.trans.shared.b16 {%0,%1,%2,%3}, [%4];"
        : "=r"(r0), "=r"(r1), "=r"(r2), "=r"(r3) : "r"(addr));
}
__device__ __forceinline__ uint32 smem_u32(const void* p) {
    uint32 a;
    asm("{ .reg .u64 t; cvta.to.shared.u64 t, %1; cvt.u32.u64 %0, t; }" : "=r"(a) : "l"(p));
    return a;
}
#define CPA4(dst, src)  asm volatile("cp.async.ca.shared.global [%0], [%1], 4;" :: "r"(dst), "l"(src) : "memory")
#define CPA16(dst, src) asm volatile("cp.async.cg.shared.global [%0], [%1], 16;" :: "r"(dst), "l"(src) : "memory")
#define CPA_COMMIT()    asm volatile("cp.async.commit_group;" ::: "memory")
#define CPA_WAIT(n)     asm volatile("cp.async.wait_group %0;" :: "n"(n) : "memory")

// ---------------- scratch (bf16 planes as packed uint32 words) ----------------
__device__ uint32 g_xnh[(size_t)NTOK * 128];
__device__ uint32 g_xnl[(size_t)NTOK * 128];
__device__ uint32 g_qkvh[(size_t)NTOK * 384];   // [t][384w], head-deinterleaved, q pre-scaled
__device__ uint32 g_qkvl[(size_t)NTOK * 384];
__device__ float  g_xc [(size_t)NTOK * C_];     // lepe fp32, PERMUTED channels [br][head][d]
__device__ uint32 g_xch[(size_t)NTOK * 128];    // attn+lepe hi (permuted)
__device__ uint32 g_xcl[(size_t)NTOK * 128];
__device__ uint32 g_wqh[768 * 128];
__device__ uint32 g_wql[768 * 128];
__device__ uint32 g_pwh[256 * 128];             // proj W, columns permuted
__device__ uint32 g_pwl[256 * 128];

template<int BR>
__device__ __forceinline__ int win_tok(int win, int s) {
    int b  = win >> 5;
    int wi = win & 31;
    int y, x;
    if (BR == 0) { y = s >> 2;               x = (wi << 2) + (s & 3); }
    else         { y = (wi << 2) + (s >> 7); x = s & 127; }
    return b * HW + y * W_ + x;
}

// ---------------- 1) LayerNorm -> bf16 hi/lo planes ----------------
__global__ void __launch_bounds__(256) ln_kernel(const float* __restrict__ x,
                                                 const float* __restrict__ gam,
                                                 const float* __restrict__ bet) {
    __shared__ float xs[C_][33];
    __shared__ float mu_s[32], rs_s[32];
    int tid = threadIdx.x;
    int tx = tid & 31, ty = tid >> 5;
    int t0 = blockIdx.x * 32;
    int b  = t0 / HW;
    int pp = t0 - b * HW;
    const float* xb = x + (size_t)b * C_ * HW + pp + tx;
    #pragma unroll
    for (int c = ty; c < C_; c += 8)
        xs[c][tx] = xb[(size_t)c * HW];
    __syncthreads();
    if (tid < 32) {
        float s = 0.f, s2 = 0.f;
        #pragma unroll 8
        for (int c = 0; c < C_; c++) { float v = xs[c][tid]; s += v; s2 += v * v; }
        float mu  = s * (1.0f / C_);
        float var = s2 * (1.0f / C_) - mu * mu;
        mu_s[tid] = mu;
        rs_s[tid] = rsqrtf(var + EPS);
    }
    __syncthreads();
    for (int idx = tid; idx < 32 * 128; idx += 256) {
        int c2 = idx & 127, tk = idx >> 7;
        int c = c2 * 2;
        float v0 = (xs[c][tk]     - mu_s[tk]) * rs_s[tk] * gam[c]     + bet[c];
        float v1 = (xs[c + 1][tk] - mu_s[tk]) * rs_s[tk] * gam[c + 1] + bet[c + 1];
        uint32 hw = pkbf(v0, v1);
        uint32 lw = pkbf(v0 - bflo(hw), v1 - bfhi(hw));
        size_t o = (size_t)(t0 + tk) * 128 + c2;
        g_xnh[o] = hw;
        g_xnl[o] = lw;
    }
}

// ---------------- 1b) weight splits (proj columns permuted) ----------------
__global__ void __launch_bounds__(256) w_split(const float* __restrict__ wqkv,
                                               const float* __restrict__ projw) {
    int idx = blockIdx.x * 256 + threadIdx.x;
    if (idx < 768 * 128) {
        int n = idx >> 7, kw = idx & 127;
        float v0 = wqkv[(size_t)(2 * kw) * 768 + n];
        float v1 = wqkv[(size_t)(2 * kw + 1) * 768 + n];
        uint32 hw = pkbf(v0, v1);
        g_wqh[idx] = hw;
        g_wql[idx] = pkbf(v0 - bflo(hw), v1 - bfhi(hw));
    }
    if (idx < 256 * 128) {
        int o = idx >> 7, kw = idx & 127;
        int pc = 2 * kw;
        int br = pc >> 7, rm = pc & 127;
        int head = rm >> 6, d = rm & 63;
        int c0 = br * 128 + 2 * d + head;
        float v0 = projw[(size_t)o * 256 + c0];
        float v1 = projw[(size_t)o * 256 + c0 + 2];
        uint32 hw = pkbf(v0, v1);
        g_pwh[idx] = hw;
        g_pwl[idx] = pkbf(v0 - bflo(hw), v1 - bfhi(hw));
    }
}

// ---------------- bf16 3-product GEMM core, cp.async double-buffered ----------------
// buffer b at b*10240 words: AH +0, AL +2560, BH +5120, BL +7680 (row stride 20 words)
#define GBUF 10240
#define SMEM_GEMM_BYTES (20480 * 4)   // 80 KB buffers; D staging (16512 w) overlays

extern __shared__ uint32 smw[];

__device__ __forceinline__ void gemm_issue(uint32 smbase, int ck,
        const uint32* __restrict__ Ah, const uint32* __restrict__ Al,
        const uint32* __restrict__ Bh, const uint32* __restrict__ Bl,
        int m0, int n0, int tid) {
    int k0w = ck * 16;
    int kb  = (ck & 1) * GBUF;
    #pragma unroll
    for (int i = 0; i < 2; i++) {
        int idx = i * 256 + tid;            // 512 total: r = idx>>2, q = (idx&3)*4
        int r = idx >> 2, q = (idx & 3) * 4;
        uint32 so = smbase + (kb + r * 20 + q) * 4;
        size_t ga = (size_t)(m0 + r) * 128 + k0w + q;
        size_t gb = (size_t)(n0 + r) * 128 + k0w + q;
        CPA16(so,            Ah + ga);
        CPA16(so + 2560 * 4, Al + ga);
        CPA16(so + 5120 * 4, Bh + gb);
        CPA16(so + 7680 * 4, Bl + gb);
    }
    CPA_COMMIT();
}

__device__ __forceinline__ void bf_mainloop(
        const uint32* __restrict__ Ah, const uint32* __restrict__ Al,
        const uint32* __restrict__ Bh, const uint32* __restrict__ Bl,
        int m0, int n0, float acc[4][4][4]) {
    int tid  = threadIdx.x;
    int wid  = tid >> 5, lane = tid & 31;
    int wm   = (wid & 1) * 64;
    int wn   = (wid >> 1) * 32;
    int grp  = lane >> 2, tig = lane & 3;
    uint32 smbase = smem_u32(smw);

    gemm_issue(smbase, 0, Ah, Al, Bh, Bl, m0, n0, tid);

    for (int ck = 0; ck < 8; ck++) {
        if (ck < 7) {
            gemm_issue(smbase, ck + 1, Ah, Al, Bh, Bl, m0, n0, tid);
            CPA_WAIT(1);
        } else {
            CPA_WAIT(0);
        }
        __syncthreads();
        int kb = (ck & 1) * GBUF;
        #pragma unroll
        for (int ks = 0; ks < 2; ks++) {
            uint32 bh[4][2], bl[4][2];
            #pragma unroll
            for (int j = 0; j < 4; j++) {
                int nb = kb + 5120 + (wn + j * 8 + grp) * 20 + ks * 8 + tig;
                bh[j][0] = smw[nb];        bh[j][1] = smw[nb + 4];
                bl[j][0] = smw[nb + 2560]; bl[j][1] = smw[nb + 2564];
            }
            #pragma unroll
            for (int i = 0; i < 4; i++) {
                int mb = kb + (wm + i * 16 + grp) * 20 + ks * 8 + tig;
                uint32 ah[4], al[4];
                ah[0] = smw[mb];           ah[1] = smw[mb + 160];
                ah[2] = smw[mb + 4];       ah[3] = smw[mb + 164];
                al[0] = smw[mb + 2560];    al[1] = smw[mb + 2720];
                al[2] = smw[mb + 2564];    al[3] = smw[mb + 2724];
                #pragma unroll
                for (int j = 0; j < 4; j++) {
                    mmabf(acc[i][j], ah, bh[j][0], bh[j][1]);
                    mmabf(acc[i][j], ah, bl[j][0], bl[j][1]);
                    mmabf(acc[i][j], al, bh[j][0], bh[j][1]);
                }
            }
        }
        __syncthreads();   // protect buffer (ck&1) before iteration ck+2's issue
    }
    // stage D (overlays buffers; safe after final sync)
    float* smf = (float*)smw;
    #pragma unroll
    for (int i = 0; i < 4; i++)
        #pragma unroll
        for (int j = 0; j < 4; j++) {
            int m = wm + i * 16 + grp;
            int n = wn + j * 8 + tig * 2;
            smf[m * 129 + n]           = acc[i][j][0];
            smf[m * 129 + n + 1]       = acc[i][j][1];
            smf[(m + 8) * 129 + n]     = acc[i][j][2];
            smf[(m + 8) * 129 + n + 1] = acc[i][j][3];
        }
    __syncthreads();
}

// ---------------- 2) QKV GEMM -> permuted bf16 planes (q pre-scaled) ----------------
__global__ void __launch_bounds__(256) gemm_qkv_bf() {
    float acc[4][4][4] = {};
    int m0 = blockIdx.y * 128;
    int n0 = blockIdx.x * 128;
    bf_mainloop(g_xnh, g_xnl, g_wqh, g_wql, m0, n0, acc);
    const float* smf = (const float*)smw;
    int tid = threadIdx.x;
    float sc = (n0 < 256) ? SCALE : 1.0f;
    for (int i = tid; i < 128 * 64; i += 256) {
        int m = i >> 6, e = i & 63;
        int head = e >> 5, d = (e & 31) * 2;
        int c0 = 2 * d + head;
        float v0 = smf[m * 129 + c0] * sc;
        float v1 = smf[m * 129 + c0 + 2] * sc;
        uint32 hw = pkbf(v0, v1);
        uint32 lw = pkbf(v0 - bflo(hw), v1 - bfhi(hw));
        size_t o = (size_t)(m0 + m) * 384 + (n0 >> 1) + e;
        g_qkvh[o] = hw;
        g_qkvl[o] = lw;
    }
}

// ---------------- 5) Proj GEMM -> channel-major fp32 out + bias ----------------
__global__ void __launch_bounds__(256) gemm_proj_bf(const float* __restrict__ Pb,
                                                    float* __restrict__ out) {
    float acc[4][4][4] = {};
    int m0 = blockIdx.y * 128;
    int n0 = blockIdx.x * 128;
    bf_mainloop(g_xch, g_xcl, g_pwh, g_pwl, m0, n0, acc);
    const float* smf = (const float*)smw;
    int tid = threadIdx.x;
    int b  = m0 >> 14;
    int pp = m0 & (HW - 1);
    int mm = tid & 127;
    int oh = tid >> 7;
    float* Op = out + (size_t)b * C_ * HW + pp + mm;
    #pragma unroll 4
    for (int oo = 0; oo < 64; oo++) {
        int o = n0 + oh * 64 + oo;
        Op[(size_t)o * HW] = smf[mm * 129 + oh * 64 + oo] + Pb[o];
    }
}

// ---------------- 3) LePE — rolling 3x3, 4 outputs/thread along long axis ----------------
// thread: (token group, ew). ew -> 2 channels: cc0 = 4*(ew&31)+(ew>>5), cc1 = cc0+2.
template<int BR>
__global__ void __launch_bounds__(256) lepe_t(const float* __restrict__ wt,
                                              const float* __restrict__ bs) {
    __shared__ float ws[128 * 9];
    __shared__ float bss[128];
    int tid = threadIdx.x;
    for (int i = tid; i < 128 * 9; i += 256) ws[i] = wt[i];
    if (tid < 128) bss[tid] = bs[tid];
    __syncthreads();
    int ew  = tid & 63;
    int gid = blockIdx.x * 4 + (tid >> 6);   // 0..16383
    int vw  = 256 + BR * 64 + ew;
    int cc0 = 4 * (ew & 31) + (ew >> 5);
    int cc1 = cc0 + 2;
    float w0[9], w1[9];
    #pragma unroll
    for (int j = 0; j < 9; j++) { w0[j] = ws[cc0 * 9 + j]; w1[j] = ws[cc1 * 9 + j]; }
    float bias0 = bss[cc0], bias1 = bss[cc1];

    // coords: BR=0: fixed x, roll y0..y0+3. BR=1: fixed y, roll x0..x0+3.
    int b, x, y, lo0;                 // lo0 = first long-axis coord
    bool lm, rm;                      // cross-axis (short-axis / full-image) masks
    if (BR == 0) {
        x = gid & 127; lo0 = ((gid >> 7) & 31) * 4; b = gid >> 12;
        lm = (x & 3) > 0; rm = (x & 3) < 3;
    } else {
        lo0 = (gid & 31) * 4; y = (gid >> 5) & 127; b = gid >> 12;
        lm = (y & 3) > 0; rm = (y & 3) < 3;
    }
    int bbase = b * HW;

    // ring rows: r0 = long-1, r1 = long, r2 = long+1; each [3 cross-taps][2 ch]
    float r0[3][2], r1[3][2], r2[3][2];
    auto loadrow = [&](int lc, float dst[3][2]) {
        bool ok = (lc >= 0) && (lc < ((BR == 0) ? 128 : 128));
        #pragma unroll
        for (int c = 0; c < 3; c++) { dst[c][0] = 0.f; dst[c][1] = 0.f; }
        if (!ok) return;
        int tb = (BR == 0) ? (bbase + lc * W_ + x) : (bbase + y * W_ + lc);
        int cs = (BR == 0) ? 1 : W_;           // cross-axis stride in tokens
        #pragma unroll
        for (int c = 0; c < 3; c++) {
            if (c == 0 && !lm) continue;
            if (c == 2 && !rm) continue;
            size_t g = (size_t)(tb + (c - 1) * cs) * 384 + vw;
            uint32 hw = g_qkvh[g], lw = g_qkvl[g];
            dst[c][0] = bflo(hw) + bflo(lw);
            dst[c][1] = bfhi(hw) + bfhi(lw);
        }
    };
    // NOTE: for BR=0 long axis is y (stride W_), cross axis is x (stride 1);
    // for BR=1 long axis is x (stride 1), cross axis is y (stride W_).
    // loadrow's tb/cs above already encode this (lc = long coord).

    loadrow(lo0 - 1, r0);
    loadrow(lo0,     r1);
    #pragma unroll
    for (int k = 0; k < 4; k++) {
        int lc = lo0 + k;
        loadrow(lc + 1, r2);
        // weight index: BR=0 rows are ki (y), cols kj (x): w[ki*3+kj], long=ki, cross=kj
        //               BR=1 long=x=kj, cross=y=ki: w[ki*3+kj] with ki=cross, kj=long
        float a0 = bias0, a1 = bias1;
        #pragma unroll
        for (int c = 0; c < 3; c++) {
            int i0, i1k, i2;
            if (BR == 0) { i0 = 0 * 3 + c; i1k = 1 * 3 + c; i2 = 2 * 3 + c; }
            else         { i0 = c * 3 + 0; i1k = c * 3 + 1; i2 = c * 3 + 2; }
            a0 += w0[i0] * r0[c][0] + w0[i1k] * r1[c][0] + w0[i2] * r2[c][0];
            a1 += w1[i0] * r0[c][1] + w1[i1k] * r1[c][1] + w1[i2] * r2[c][1];
        }
        int t = (BR == 0) ? (bbase + lc * W_ + x) : (bbase + y * W_ + lc);
        *(float2*)&g_xc[(size_t)t * 256 + BR * 128 + 2 * ew] = make_float2(a0, a1);
        #pragma unroll
        for (int c = 0; c < 3; c++) {
            r0[c][0] = r1[c][0]; r0[c][1] = r1[c][1];
            r1[c][0] = r2[c][0]; r1[c][1] = r2[c][1];
        }
    }
}

// ---------------- 4) Flash attention — cp.async double-buffered K/V ----------------
#define AQH 0
#define AQL 4608
#define SMEM_ATTN_BYTES (27648 * 4)   // 110,592 B -> 2 CTAs/SM

extern __shared__ uint32 smaw[];
template<int BR>
__global__ void __launch_bounds__(256, 2) attn_flash() {
    int qt   = blockIdx.x;
    int head = blockIdx.y;
    int win  = blockIdx.z;
    int tid  = threadIdx.x;
    int wid  = tid >> 5, lane = tid & 31;
    int grp  = lane >> 2, tig = lane & 3;
    int basew = BR * 64 + head * 32;
    uint32 smbase = smem_u32(smaw);

    {
        int kb = 9216;
        #pragma unroll
        for (int i = 0; i < 8; i++) {
            int idx = i * 256 + tid;
            int r = idx >> 5, w = idx & 31;
            int t = win_tok<BR>(win, r);
            size_t gk = (size_t)t * 384 + 128 + basew + w;
            size_t gv = (size_t)t * 384 + 256 + basew + w;
            uint32 so = smbase + (kb + r * 36 + w) * 4;
            CPA4(so,            g_qkvh + gk);
            CPA4(so + 2304 * 4, g_qkvl + gk);
            CPA4(so + 4608 * 4, g_qkvh + gv);
            CPA4(so + 6912 * 4, g_qkvl + gv);
        }
        CPA_COMMIT();
    }
    for (int idx = tid; idx < 4096; idx += 256) {
        int r = idx >> 5, w = idx & 31;
        int t = win_tok<BR>(win, qt * 128 + r);
        size_t g = (size_t)t * 384 + basew + w;
        smaw[AQH + r * 36 + w] = g_qkvh[g];
        smaw[AQL + r * 36 + w] = g_qkvl[g];
    }
    __syncthreads();

    uint32 qh[4][4], ql[4][4];
    {
        int rb = (wid * 16 + grp) * 36 + tig;
        #pragma unroll
        for (int ks = 0; ks < 4; ks++) {
            int o = rb + ks * 8;
            qh[ks][0] = smaw[AQH + o];       qh[ks][1] = smaw[AQH + o + 288];
            qh[ks][2] = smaw[AQH + o + 4];   qh[ks][3] = smaw[AQH + o + 292];
            ql[ks][0] = smaw[AQL + o];       ql[ks][1] = smaw[AQL + o + 288];
            ql[ks][2] = smaw[AQL + o + 4];   ql[ks][3] = smaw[AQL + o + 292];
        }
    }

    float o_acc[8][4] = {};
    float m0 = -1e30f, m1 = -1e30f, l0 = 0.f, l1 = 0.f;

    for (int ck = 0; ck < 8; ck++) {
        if (ck < 7) {
            int kb = 9216 + ((ck + 1) & 1) * 9216;
            #pragma unroll
            for (int i = 0; i < 8; i++) {
                int idx = i * 256 + tid;
                int r = idx >> 5, w = idx & 31;
                int t = win_tok<BR>(win, (ck + 1) * 64 + r);
                size_t gk = (size_t)t * 384 + 128 + basew + w;
                size_t gv = (size_t)t * 384 + 256 + basew + w;
                uint32 so = smbase + (kb + r * 36 + w) * 4;
                CPA4(so,            g_qkvh + gk);
                CPA4(so + 2304 * 4, g_qkvl + gk);
                CPA4(so + 4608 * 4, g_qkvh + gv);
                CPA4(so + 6912 * 4, g_qkvl + gv);
            }
            CPA_COMMIT();
            CPA_WAIT(1);
        } else {
            CPA_WAIT(0);
        }
        __syncthreads();

        int kb  = 9216 + (ck & 1) * 9216;
        int akh = kb, akl = kb + 2304, avh = kb + 4608, avl = kb + 6912;

        float s[8][4];
        #pragma unroll
        for (int j = 0; j < 8; j++) {
            s[j][0] = s[j][1] = s[j][2] = s[j][3] = 0.f;
            #pragma unroll
            for (int ks = 0; ks < 4; ks++) {
                int nb = (j * 8 + grp) * 36 + ks * 8 + tig;
                uint32 bh0 = smaw[akh + nb], bh1 = smaw[akh + nb + 4];
                uint32 bl0 = smaw[akl + nb], bl1 = smaw[akl + nb + 4];
                mmabf(s[j], qh[ks], bh0, bh1);
                mmabf(s[j], qh[ks], bl0, bl1);
                mmabf(s[j], ql[ks], bh0, bh1);
            }
        }

        float mx0 = s[0][0], mx1 = s[0][2];
        #pragma unroll
        for (int j = 0; j < 8; j++) {
            mx0 = fmaxf(mx0, fmaxf(s[j][0], s[j][1]));
            mx1 = fmaxf(mx1, fmaxf(s[j][2], s[j][3]));
        }
        mx0 = fmaxf(mx0, __shfl_xor_sync(0xffffffffu, mx0, 1));
        mx0 = fmaxf(mx0, __shfl_xor_sync(0xffffffffu, mx0, 2));
        mx1 = fmaxf(mx1, __shfl_xor_sync(0xffffffffu, mx1, 1));
        mx1 = fmaxf(mx1, __shfl_xor_sync(0xffffffffu, mx1, 2));
        float mn0 = fmaxf(m0, mx0), mn1 = fmaxf(m1, mx1);
        float sf0 = __expf(m0 - mn0), sf1 = __expf(m1 - mn1);
        m0 = mn0; m1 = mn1;
        float rs0 = 0.f, rs1 = 0.f;
        #pragma unroll
        for (int j = 0; j < 8; j++) {
            s[j][0] = __expf(s[j][0] - m0); rs0 += s[j][0];
            s[j][1] = __expf(s[j][1] - m0); rs0 += s[j][1];
            s[j][2] = __expf(s[j][2] - m1); rs1 += s[j][2];
            s[j][3] = __expf(s[j][3] - m1); rs1 += s[j][3];
        }
        rs0 += __shfl_xor_sync(0xffffffffu, rs0, 1);
        rs0 += __shfl_xor_sync(0xffffffffu, rs0, 2);
        rs1 += __shfl_xor_sync(0xffffffffu, rs1, 1);
        rs1 += __shfl_xor_sync(0xffffffffu, rs1, 2);
        l0 = l0 * sf0 + rs0;
        l1 = l1 * sf1 + rs1;
        #pragma unroll
        for (int j = 0; j < 8; j++) {
            o_acc[j][0] *= sf0; o_acc[j][1] *= sf0;
            o_acc[j][2] *= sf1; o_acc[j][3] *= sf1;
        }

        int p2 = lane >> 3, rr = lane & 7;
        #pragma unroll
        for (int ks = 0; ks < 4; ks++) {
            int j0 = 2 * ks, j1 = 2 * ks + 1;
            uint32 ph[4], pl[4];
            ph[0] = pkbf(s[j0][0], s[j0][1]);
            ph[1] = pkbf(s[j0][2], s[j0][3]);
            ph[2] = pkbf(s[j1][0], s[j1][1]);
            ph[3] = pkbf(s[j1][2], s[j1][3]);
            pl[0] = pkbf(s[j0][0] - bflo(ph[0]), s[j0][1] - bfhi(ph[0]));
            pl[1] = pkbf(s[j0][2] - bflo(ph[1]), s[j0][3] - bfhi(ph[1]));
            pl[2] = pkbf(s[j1][0] - bflo(ph[2]), s[j1][1] - bfhi(ph[2]));
            pl[3] = pkbf(s[j1][2] - bflo(ph[3]), s[j1][3] - bfhi(ph[3]));
            int key = 16 * ks + ((p2 & 1) << 3) + rr;
            #pragma unroll
            for (int jp = 0; jp < 4; jp++) {
                int dw = (16 * jp + ((p2 >> 1) << 3)) >> 1;
                uint32 aH = smbase + (avh + key * 36 + dw) * 4;
                uint32 aL = smbase + (avl + key * 36 + dw) * 4;
                uint32 vh0, vh1, vh2, vh3, vl0, vl1, vl2, vl3;
                ldmT(vh0, vh1, vh2, vh3, aH);
                ldmT(vl0, vl1, vl2, vl3, aL);
                mmabf(o_acc[2 * jp],     ph, vh0, vh1);
                mmabf(o_acc[2 * jp],     ph, vl0, vl1);
                mmabf(o_acc[2 * jp],     pl, vh0, vh1);
                mmabf(o_acc[2 * jp + 1], ph, vh2, vh3);
                mmabf(o_acc[2 * jp + 1], ph, vl2, vl3);
                mmabf(o_acc[2 * jp + 1], pl, vh2, vh3);
            }
        }
        __syncthreads();
    }

    float i0 = 1.0f / l0, i1 = 1.0f / l1;
    int r0 = qt * 128 + wid * 16 + grp;
    int t0 = win_tok<BR>(win, r0);
    int t1 = win_tok<BR>(win, r0 + 8);
    int cb  = BR * 128 + head * 64;
    int wb0 = BR * 64 + head * 32;
    #pragma unroll
    for (int j = 0; j < 8; j++) {
        int d = j * 8 + 2 * tig;
        float2 le0 = *(const float2*)&g_xc[(size_t)t0 * 256 + cb + d];
        float2 le1 = *(const float2*)&g_xc[(size_t)t1 * 256 + cb + d];
        float a0 = le0.x + o_acc[j][0] * i0;
        float a1 = le0.y + o_acc[j][1] * i0;
        float b0 = le1.x + o_acc[j][2] * i1;
        float b1 = le1.y + o_acc[j][3] * i1;
        int wx = wb0 + j * 4 + tig;
        uint32 h0 = pkbf(a0, a1);
        g_xch[(size_t)t0 * 128 + wx] = h0;
        g_xcl[(size_t)t0 * 128 + wx] = pkbf(a0 - bflo(h0), a1 - bfhi(h0));
        uint32 h1 = pkbf(b0, b1);
        g_xch[(size_t)t1 * 128 + wx] = h1;
        g_xcl[(size_t)t1 * 128 + wx] = pkbf(b0 - bflo(h1), b1 - bfhi(h1));
    }
}

// ---------------- launch ----------------
extern "C" void kernel_launch(void* const* d_in, const int* in_sizes, int n_in,
                              void* d_out, int out_size) {
    const float* x       = (const float*)d_in[0];
    const float* ln_g    = (const float*)d_in[1];
    const float* ln_b    = (const float*)d_in[2];
    const float* w_qkv   = (const float*)d_in[3];
    const float* lepe_w1 = (const float*)d_in[4];
    const float* lepe_b1 = (const float*)d_in[5];
    const float* lepe_w2 = (const float*)d_in[6];
    const float* lepe_b2 = (const float*)d_in[7];
    const float* proj_w  = (const float*)d_in[8];
    const float* proj_b  = (const float*)d_in[9];
    float* out = (float*)d_out;

    cudaFuncSetAttribute(gemm_qkv_bf,  cudaFuncAttributeMaxDynamicSharedMemorySize, SMEM_GEMM_BYTES);
    cudaFuncSetAttribute(gemm_proj_bf, cudaFuncAttributeMaxDynamicSharedMemorySize, SMEM_GEMM_BYTES);
    cudaFuncSetAttribute(attn_flash<0>, cudaFuncAttributeMaxDynamicSharedMemorySize, SMEM_ATTN_BYTES);
    cudaFuncSetAttribute(attn_flash<1>, cudaFuncAttributeMaxDynamicSharedMemorySize, SMEM_ATTN_BYTES);

    ln_kernel   <<< NTOK / 32, 256 >>>(x, ln_g, ln_b);
    w_split     <<< 384, 256 >>>(w_qkv, proj_w);
    gemm_qkv_bf <<< dim3(6, 512), 256, SMEM_GEMM_BYTES >>>();
    lepe_t<0>   <<< 4096, 256 >>>(lepe_w1, lepe_b1);
    lepe_t<1>   <<< 4096, 256 >>>(lepe_w2, lepe_b2);
    attn_flash<0> <<< dim3(4, 2, 128), 256, SMEM_ATTN_BYTES >>>();
    attn_flash<1> <<< dim3(4, 2, 128), 256, SMEM_ATTN_BYTES >>>();
    gemm_proj_bf <<< dim3(2, 512), 256, SMEM_GEMM_BYTES >>>(proj_b, out);
}